// round 4
// baseline (speedup 1.0000x reference)
#include <cuda_runtime.h>

#define BB 2
#define SS 2048
#define DD 128
#define HH 8
#define EPSF 1e-10f
#define FULLM 0xffffffffu
#define TTBLK 64            // blocks doing phase-1 (4096 rows, 8 thr/row, 512 thr/blk)

// Scratch (allocation-free rule: __device__ globals; zero-init at load)
__device__ int      g_tt[BB * SS];
__device__ int2     g_lohi[BB * SS];
__device__ unsigned g_cnt  = 0;
__device__ unsigned g_flag = 0;

__device__ __forceinline__ unsigned ld_acquire_u32(const unsigned* p) {
    unsigned v;
    asm volatile("ld.acquire.gpu.global.u32 %0, [%1];" : "=r"(v) : "l"(p) : "memory");
    return v;
}

__global__ void __launch_bounds__(512) k_fused(const float* __restrict__ x,
                                               const float* __restrict__ gu,
                                               const float* __restrict__ W,
                                               const float* __restrict__ bias,
                                               float4* __restrict__ out) {
    const int tid = threadIdx.x;
    const int bid = blockIdx.x;

    __shared__ int sh_last;
    __shared__ int sh_wmin[16];
    __shared__ int sh_wsuf[16];

    // ======================= Phase 1: blocks 0..63 =======================
    if (bid < TTBLK) {
        // --- token-type argmax: 8 threads per (b,s) row ---
        int gid = bid * 512 + tid;
        int row = gid >> 3;            // 0..4095
        int r   = gid & 7;

        const float4* xr = reinterpret_cast<const float4*>(x + (size_t)row * DD);
        const float4* W4 = reinterpret_cast<const float4*>(W);

        float4 xv[4];
        #pragma unroll
        for (int i = 0; i < 4; i++) xv[i] = xr[r * 4 + i];

        float a0 = 0.f, a1 = 0.f, a2 = 0.f;
        #pragma unroll
        for (int i = 0; i < 4; i++) {
            int c = r * 4 + i;
            float4 w0 = W4[c];
            float4 w1 = W4[32 + c];
            float4 w2 = W4[64 + c];
            a0 += xv[i].x * w0.x + xv[i].y * w0.y + xv[i].z * w0.z + xv[i].w * w0.w;
            a1 += xv[i].x * w1.x + xv[i].y * w1.y + xv[i].z * w1.z + xv[i].w * w1.w;
            a2 += xv[i].x * w2.x + xv[i].y * w2.y + xv[i].z * w2.z + xv[i].w * w2.w;
        }
        #pragma unroll
        for (int off = 4; off; off >>= 1) {
            a0 += __shfl_xor_sync(FULLM, a0, off);
            a1 += __shfl_xor_sync(FULLM, a1, off);
            a2 += __shfl_xor_sync(FULLM, a2, off);
        }
        if (r == 0) {
            const float* gr = gu + (size_t)row * 3;
            float g0 = -logf(-logf(gr[0] + EPSF) + EPSF);
            float g1 = -logf(-logf(gr[1] + EPSF) + EPSF);
            float g2 = -logf(-logf(gr[2] + EPSF) + EPSF);
            float s0 = a0 + bias[0] + g0;
            float s1 = a1 + bias[1] + g1;
            float s2 = a2 + bias[2] + g2;
            int tt = 0; float best = s0;
            if (s1 > best) { best = s1; tt = 1; }   // first-max tie-break
            if (s2 > best) { best = s2; tt = 2; }
            g_tt[row] = tt;
        }
        __syncthreads();
        if (tid == 0) {
            __threadfence();                              // release g_tt
            sh_last = (atomicAdd(&g_cnt, 1u) == TTBLK - 1);
        }
        __syncthreads();

        // --- last block: suffix-min scan per batch, publish (lo,hi) ---
        if (sh_last) {
            __threadfence();                              // acquire all g_tt
            int lane = tid & 31, wid = tid >> 5;          // 16 warps
            for (int b = 0; b < BB; b++) {
                __syncthreads();                          // shared reuse guard
                int base = b * SS + tid * 4;              // 4 elems/thread
                int t0 = g_tt[base + 0], t1 = g_tt[base + 1];
                int t2 = g_tt[base + 2], t3 = g_tt[base + 3];
                int j0 = tid * 4;
                int e0 = (t0 == 0) ? j0     : SS;
                int e1 = (t1 == 0) ? j0 + 1 : SS;
                int e2 = (t2 == 0) ? j0 + 2 : SS;
                int e3 = (t3 == 0) ? j0 + 3 : SS;
                int m = min(min(e0, e1), min(e2, e3));

                // inclusive suffix-min within warp (lanes ascend with index)
                int inc = m;
                #pragma unroll
                for (int off = 1; off < 32; off <<= 1) {
                    int v = __shfl_down_sync(FULLM, inc, off);
                    if (lane + off < 32) inc = min(inc, v);
                }
                int excl = __shfl_down_sync(FULLM, inc, 1);
                if (lane == 31) excl = SS;

                if (lane == 0) sh_wmin[wid] = inc;
                __syncthreads();
                if (wid == 0) {
                    int wm = (lane < 16) ? sh_wmin[lane] : SS;
                    int winc = wm;
                    #pragma unroll
                    for (int off = 1; off < 16; off <<= 1)
                        winc = min(winc, __shfl_down_sync(FULLM, winc, off));
                    int wex = __shfl_down_sync(FULLM, winc, 1);  // lane15 reads SS
                    if (lane == 15) { /* wex already SS from lane16 */ }
                    if (lane < 16) sh_wsuf[lane] = wex;
                }
                __syncthreads();
                int after = min(excl, sh_wsuf[wid]);      // min over idx > 4t+3

                // right-to-left: ng[j] = min over gidx[j+1..]
                int run = after;
                int ng3 = run; run = min(run, e3);
                int ng2 = run; run = min(run, e2);
                int ng1 = run; run = min(run, e1);
                int ng0 = run;

                int2 lh;
                #define EMIT(ii, tt_, ng_)                                  \
                    { int j = j0 + ii; lh.x = 0; lh.y = j;                  \
                      if (tt_ == 1)      { lh.x = j; lh.y = j; }            \
                      else if (tt_ == 2) { lh.y = min(j, ng_); }            \
                      g_lohi[base + ii] = lh; }
                EMIT(0, t0, ng0); EMIT(1, t1, ng1);
                EMIT(2, t2, ng2); EMIT(3, t3, ng3);
                #undef EMIT
            }
            __syncthreads();
            if (tid == 0) {
                __threadfence();           // release g_lohi
                g_cnt = 0;                 // reset for next replay
                atomicExch(&g_flag, 1u);
            }
        }
    }

    // ======================= Write role: all blocks =======================
    int row = bid;                  // over B*H*S = 32768
    int s   = row & (SS - 1);
    int b   = row >> 14;            // / (H*S)
    float4* orow = out + (size_t)row * (SS / 4);
    int q = tid;                    // one float4 per thread
    int qdiag = s >> 2;

    // Suffix zeros (tt-independent) — issue immediately, overlaps phase-1
    if (q > qdiag) {
        __stcs(&orow[q], make_float4(0.f, 0.f, 0.f, 0.f));
    }

    // Wait for (lo,hi) publication
    if (tid == 0) {
        while (ld_acquire_u32(&g_flag) == 0) __nanosleep(64);
    }
    __syncthreads();

    if (q <= qdiag) {
        int2 lh = g_lohi[b * SS + s];
        int j = q << 2;
        float4 v;
        v.x = (j     >= lh.x && j     <= lh.y) ? 1.0f : 0.0f;
        v.y = (j + 1 >= lh.x && j + 1 <= lh.y) ? 1.0f : 0.0f;
        v.z = (j + 2 >= lh.x && j + 2 <= lh.y) ? 1.0f : 0.0f;
        v.w = (j + 3 >= lh.x && j + 3 <= lh.y) ? 1.0f : 0.0f;
        __stcs(&orow[q], v);
    }
}

extern "C" void kernel_launch(void* const* d_in, const int* in_sizes, int n_in,
                              void* d_out, int out_size) {
    const float* x    = (const float*)d_in[0];  // input_tensor (B,S,D)
    // d_in[1] = token_types (unused by reference)
    const float* gu   = (const float*)d_in[2];  // gumbel_u (B,S,3)
    const float* W    = (const float*)d_in[3];  // (3,D)
    const float* bias = (const float*)d_in[4];  // (3,)
    float4* out = (float4*)d_out;

    k_fused<<<BB * HH * SS, 512>>>(x, gu, W, bias, out);
}